// round 15
// baseline (speedup 1.0000x reference)
#include <cuda_runtime.h>
#include <cstdint>

// 3x3 conv, stride 1, pad 1, single channel, X: (32, 1024, 1024) fp32.
// Bulk in BOTH directions: each CTA handles a 4-row x 1024-col band.
//   READ : 6 input rows (24KB contiguous) via ONE cp.async.bulk g->s.
//   WRITE: 4 output rows (16KB contiguous in Y) computed into an smem
//          out-buffer, then ONE cp.async.bulk s->g (bulk_group) per CTA.
// Goal: both DRAM streams become large contiguous bursts, cutting the
// read/write turnaround that pins dram__cycles_active at ~70%.
// smem 40.2KB -> 5 CTAs/SM (occ ~62%, proven sufficient in R12 vs R14).
// Compute: one-touch rolling 3-row register window.

#define IMG_W 1024
#define IMG_H 1024
#define ROWS_CTA 4
#define SM_ROWS (ROWS_CTA + 2)

__device__ __forceinline__ uint32_t smem_u32(const void* p) {
    uint32_t a;
    asm("{ .reg .u64 t; cvta.to.shared.u64 t, %1; cvt.u32.u64 %0, t; }"
        : "=r"(a) : "l"(p));
    return a;
}

__global__ __launch_bounds__(256, 5) void conv3x3_kernel(
    const float* __restrict__ X,
    const float* __restrict__ Wt,
    float* __restrict__ Y)
{
    __shared__ __align__(128) float sm_in[SM_ROWS * IMG_W];    // 24 KB
    __shared__ __align__(128) float sm_out[ROWS_CTA * IMG_W];  // 16 KB
    __shared__ __align__(8)  unsigned long long mbar;

    const int tid   = threadIdx.x;
    const int bx    = blockIdx.x;
    const int batch = bx >> 8;            // / 256 bands
    const int band  = bx & 255;
    const int r0    = band << 2;          // first output row
    const int c0    = tid << 2;           // 4 cols per thread (covers 1024)

    const size_t plane = (size_t)IMG_W * IMG_H;
    const float* Xb = X + (size_t)batch * plane;
    float*       Yb = Y + (size_t)batch * plane;

    const uint32_t mbar_a = smem_u32(&mbar);
    const uint32_t in_a   = smem_u32(sm_in);
    const uint32_t out_a  = smem_u32(sm_out);

    if (tid == 0) {
        asm volatile("mbarrier.init.shared.b64 [%0], 1;" :: "r"(mbar_a) : "memory");
    }
    __syncthreads();

    // One contiguous bulk copy in: gmem rows [gstart, gend] -> smem.
    const int r_first = r0 - 1;
    const int gstart  = r_first < 0 ? 0 : r_first;
    const int gend_i  = r0 + ROWS_CTA;                 // halo row below
    const int gend    = gend_i > (IMG_H - 1) ? (IMG_H - 1) : gend_i;
    const uint32_t nbytes = (uint32_t)(gend - gstart + 1) * IMG_W * 4u;
    const uint32_t dst    = in_a + (uint32_t)(gstart - r_first) * IMG_W * 4u;
    const float*   src    = Xb + (size_t)gstart * IMG_W;

    if (tid == 0) {
        asm volatile("mbarrier.arrive.expect_tx.shared.b64 _, [%0], %1;"
                     :: "r"(mbar_a), "r"(nbytes) : "memory");
        asm volatile(
            "cp.async.bulk.shared::cta.global.mbarrier::complete_tx::bytes "
            "[%0], [%1], %2, [%3];"
            :: "r"(dst), "l"(src), "r"(nbytes), "r"(mbar_a) : "memory");
    }

    // Zero pad rows (never written by the copy) while the copy is in flight.
    if (r_first < 0) {
        float4 z = make_float4(0.f, 0.f, 0.f, 0.f);
        *reinterpret_cast<float4*>(&sm_in[c0]) = z;
    }
    if (gend_i > IMG_H - 1) {
        float4 z = make_float4(0.f, 0.f, 0.f, 0.f);
        *reinterpret_cast<float4*>(&sm_in[(SM_ROWS - 1) * IMG_W + c0]) = z;
    }

    // Weights (L2-cached broadcast) while the copy is in flight.
    float w[9];
#pragma unroll
    for (int i = 0; i < 9; i++) w[i] = __ldg(Wt + i);

    // Wait for the bulk copy (phase 0), then sync so pad zeros are visible.
    asm volatile(
        "{\n\t"
        ".reg .pred P;\n\t"
        "WAIT_%=:\n\t"
        "mbarrier.try_wait.parity.acquire.cta.shared::cta.b64 P, [%0], 0;\n\t"
        "@!P bra WAIT_%=;\n\t"
        "}"
        :: "r"(mbar_a) : "memory");
    __syncthreads();

    // Rolling 3-row register window; sm_in row k = input row r0 + k - 1.
    float b[3][6];

#define LOAD_SMROW(dstbuf, k)                                                 \
    do {                                                                      \
        const float* rp = &sm_in[(k) * IMG_W];                                \
        const float4 v = *reinterpret_cast<const float4*>(rp + c0);           \
        (dstbuf)[1] = v.x; (dstbuf)[2] = v.y;                                 \
        (dstbuf)[3] = v.z; (dstbuf)[4] = v.w;                                 \
        (dstbuf)[0] = (c0 > 0)           ? rp[c0 - 1] : 0.0f;                 \
        (dstbuf)[5] = (c0 + 4 < IMG_W)   ? rp[c0 + 4] : 0.0f;                 \
    } while (0)

    LOAD_SMROW(b[0], 0);
    LOAD_SMROW(b[1], 1);

#pragma unroll
    for (int i = 0; i < ROWS_CTA; i++) {
        LOAD_SMROW(b[(i + 2) % 3], i + 2);

        const float* t0 = b[i % 3];         // input row r0+i-1  (ky=0)
        const float* t1 = b[(i + 1) % 3];   // input row r0+i    (ky=1)
        const float* t2 = b[(i + 2) % 3];   // input row r0+i+1  (ky=2)

        float4 o;
        float acc[4];
#pragma unroll
        for (int j = 0; j < 4; j++) {
            float a;
            a = fmaf(w[0], t0[j], fmaf(w[1], t0[j + 1], w[2] * t0[j + 2]));
            a = fmaf(w[3], t1[j], fmaf(w[4], t1[j + 1], fmaf(w[5], t1[j + 2], a)));
            a = fmaf(w[6], t2[j], fmaf(w[7], t2[j + 1], fmaf(w[8], t2[j + 2], a)));
            acc[j] = a;
        }
        o.x = acc[0]; o.y = acc[1]; o.z = acc[2]; o.w = acc[3];
        *reinterpret_cast<float4*>(&sm_out[i * IMG_W + c0]) = o;
    }
#undef LOAD_SMROW

    // All STS visible CTA-wide, then order generic->async proxy and emit the
    // whole 16KB band as one bulk store. tid 0 waits for the group so smem
    // is not freed under the in-flight read.
    __syncthreads();
    if (tid == 0) {
        asm volatile("fence.proxy.async.shared::cta;" ::: "memory");
        const float* gdst = Yb + (size_t)r0 * IMG_W;
        const uint32_t outb = (uint32_t)(ROWS_CTA * IMG_W * 4u);
        asm volatile(
            "cp.async.bulk.global.shared::cta.bulk_group [%0], [%1], %2;"
            :: "l"(gdst), "r"(out_a), "r"(outb) : "memory");
        asm volatile("cp.async.bulk.commit_group;" ::: "memory");
        asm volatile("cp.async.bulk.wait_group 0;" ::: "memory");
    }
}

extern "C" void kernel_launch(void* const* d_in, const int* in_sizes, int n_in,
                              void* d_out, int out_size)
{
    const float* X  = (const float*)d_in[0];   // (32, 1024, 1024) fp32
    const float* Wt = (const float*)d_in[1];   // (3, 3) fp32
    float* Y        = (float*)d_out;           // (32, 1024, 1024) fp32

    const int grid = 32 * 256;                 // batches * 4-row bands
    conv3x3_kernel<<<grid, 256>>>(X, Wt, Y);
}

// round 16
// speedup vs baseline: 1.0156x; 1.0156x over previous
#include <cuda_runtime.h>
#include <cstdint>

// 3x3 conv, stride 1, pad 1, single channel, X: (32, 1024, 1024) fp32.
// 8-row band per CTA with a TWO-STAGE pipelined bulk read:
//   chunk A: input rows r0-1..r0+4 (24KB) -> bufA   (mbarA)
//   chunk B: input rows r0+5..r0+8 (16KB) -> bufB   (mbarB)
// Both copies are issued back-to-back; outputs r0..r0+3 are computed from
// bufA while chunk B streams in, then r0+4..r0+7 complete from bufA tail +
// bufB. Same 40.3KB smem / 5 CTAs/SM as the best-kernel R10, but ~40% less
// exposed copy latency per CTA. One-touch rolling 3-row register window;
// __stcs float4 stores. Grid 4096 one-shot CTAs.

#define IMG_W 1024
#define IMG_H 1024
#define ROWS_CTA 8
#define A_ROWS 6               // input rows r0-1 .. r0+4
#define B_ROWS 4               // input rows r0+5 .. r0+8

__device__ __forceinline__ uint32_t smem_u32(const void* p) {
    uint32_t a;
    asm("{ .reg .u64 t; cvta.to.shared.u64 t, %1; cvt.u32.u64 %0, t; }"
        : "=r"(a) : "l"(p));
    return a;
}

__global__ __launch_bounds__(256, 5) void conv3x3_kernel(
    const float* __restrict__ X,
    const float* __restrict__ Wt,
    float* __restrict__ Y)
{
    __shared__ __align__(128) float bufA[A_ROWS * IMG_W];   // 24 KB
    __shared__ __align__(128) float bufB[B_ROWS * IMG_W];   // 16 KB
    __shared__ __align__(8)  unsigned long long mbar[2];

    const int tid   = threadIdx.x;
    const int bx    = blockIdx.x;
    const int batch = bx >> 7;            // / 128 bands
    const int band  = bx & 127;
    const int r0    = band << 3;          // first output row
    const int c0    = tid << 2;           // 4 cols per thread (covers 1024)

    const size_t plane = (size_t)IMG_W * IMG_H;
    const float* Xb = X + (size_t)batch * plane;
    float*       Yb = Y + (size_t)batch * plane;

    const uint32_t mbarA = smem_u32(&mbar[0]);
    const uint32_t mbarB = smem_u32(&mbar[1]);
    const uint32_t a_a   = smem_u32(bufA);
    const uint32_t b_a   = smem_u32(bufB);

    if (tid == 0) {
        asm volatile("mbarrier.init.shared.b64 [%0], 1;" :: "r"(mbarA) : "memory");
        asm volatile("mbarrier.init.shared.b64 [%0], 1;" :: "r"(mbarB) : "memory");
    }
    __syncthreads();

    // Chunk A: rows max(r0-1,0) .. r0+4  (r0+4 <= 1020, always valid).
    const int aStart = (r0 - 1 < 0) ? 0 : (r0 - 1);
    const uint32_t aBytes = (uint32_t)(r0 + 4 - aStart + 1) * IMG_W * 4u;
    const uint32_t aDst   = a_a + (uint32_t)(aStart - (r0 - 1)) * IMG_W * 4u;
    // Chunk B: rows r0+5 .. min(r0+8, 1023).
    const int bEnd = (r0 + 8 > IMG_H - 1) ? (IMG_H - 1) : (r0 + 8);
    const uint32_t bBytes = (uint32_t)(bEnd - (r0 + 5) + 1) * IMG_W * 4u;

    if (tid == 0) {
        asm volatile("mbarrier.arrive.expect_tx.shared.b64 _, [%0], %1;"
                     :: "r"(mbarA), "r"(aBytes) : "memory");
        asm volatile(
            "cp.async.bulk.shared::cta.global.mbarrier::complete_tx::bytes "
            "[%0], [%1], %2, [%3];"
            :: "r"(aDst), "l"(Xb + (size_t)aStart * IMG_W), "r"(aBytes),
               "r"(mbarA) : "memory");
        asm volatile("mbarrier.arrive.expect_tx.shared.b64 _, [%0], %1;"
                     :: "r"(mbarB), "r"(bBytes) : "memory");
        asm volatile(
            "cp.async.bulk.shared::cta.global.mbarrier::complete_tx::bytes "
            "[%0], [%1], %2, [%3];"
            :: "r"(b_a), "l"(Xb + (size_t)(r0 + 5) * IMG_W), "r"(bBytes),
               "r"(mbarB) : "memory");
    }

    // Zero pad slots the copies never write (while copies are in flight).
    if (r0 == 0) {
        float4 z = make_float4(0.f, 0.f, 0.f, 0.f);
        *reinterpret_cast<float4*>(&bufA[c0]) = z;           // input row -1
    }
    if (r0 + 8 > IMG_H - 1) {
        float4 z = make_float4(0.f, 0.f, 0.f, 0.f);
        *reinterpret_cast<float4*>(&bufB[(B_ROWS - 1) * IMG_W + c0]) = z; // row 1024
    }

    float w[9];
#pragma unroll
    for (int i = 0; i < 9; i++) w[i] = __ldg(Wt + i);

    // Wait for chunk A; sync makes pad zeros visible across the CTA.
    asm volatile(
        "{\n\t"
        ".reg .pred P;\n\t"
        "WA_%=:\n\t"
        "mbarrier.try_wait.parity.acquire.cta.shared::cta.b64 P, [%0], 0;\n\t"
        "@!P bra WA_%=;\n\t"
        "}"
        :: "r"(mbarA) : "memory");
    __syncthreads();

    // Combined stream: input row (r0-1+k) lives in bufA[k] (k<6) / bufB[k-6].
    float b3[3][6];

#define LOAD_K(dstbuf, k)                                                     \
    do {                                                                      \
        const float* rp = ((k) < A_ROWS) ? &bufA[(k) * IMG_W]                 \
                                         : &bufB[((k) - A_ROWS) * IMG_W];     \
        const float4 v = *reinterpret_cast<const float4*>(rp + c0);           \
        (dstbuf)[1] = v.x; (dstbuf)[2] = v.y;                                 \
        (dstbuf)[3] = v.z; (dstbuf)[4] = v.w;                                 \
        (dstbuf)[0] = (c0 > 0)           ? rp[c0 - 1] : 0.0f;                 \
        (dstbuf)[5] = (c0 + 4 < IMG_W)   ? rp[c0 + 4] : 0.0f;                 \
    } while (0)

    LOAD_K(b3[0], 0);
    LOAD_K(b3[1], 1);

#pragma unroll
    for (int i = 0; i < ROWS_CTA; i++) {
        if (i == 4) {
            // Next row load (k=6) is the first from bufB: wait for chunk B.
            asm volatile(
                "{\n\t"
                ".reg .pred P;\n\t"
                "WB_%=:\n\t"
                "mbarrier.try_wait.parity.acquire.cta.shared::cta.b64 P, [%0], 0;\n\t"
                "@!P bra WB_%=;\n\t"
                "}"
                :: "r"(mbarB) : "memory");
        }
        LOAD_K(b3[(i + 2) % 3], i + 2);

        const float* t0 = b3[i % 3];         // input row r0+i-1  (ky=0)
        const float* t1 = b3[(i + 1) % 3];   // input row r0+i    (ky=1)
        const float* t2 = b3[(i + 2) % 3];   // input row r0+i+1  (ky=2)

        float acc[4];
#pragma unroll
        for (int j = 0; j < 4; j++) {
            float a;
            a = fmaf(w[0], t0[j], fmaf(w[1], t0[j + 1], w[2] * t0[j + 2]));
            a = fmaf(w[3], t1[j], fmaf(w[4], t1[j + 1], fmaf(w[5], t1[j + 2], a)));
            a = fmaf(w[6], t2[j], fmaf(w[7], t2[j + 1], fmaf(w[8], t2[j + 2], a)));
            acc[j] = a;
        }
        float4 o;
        o.x = acc[0]; o.y = acc[1]; o.z = acc[2]; o.w = acc[3];
        __stcs(reinterpret_cast<float4*>(Yb + (size_t)(r0 + i) * IMG_W + c0), o);
    }
#undef LOAD_K
}

extern "C" void kernel_launch(void* const* d_in, const int* in_sizes, int n_in,
                              void* d_out, int out_size)
{
    const float* X  = (const float*)d_in[0];   // (32, 1024, 1024) fp32
    const float* Wt = (const float*)d_in[1];   // (3, 3) fp32
    float* Y        = (float*)d_out;           // (32, 1024, 1024) fp32

    const int grid = 32 * 128;                 // batches * 8-row bands
    conv3x3_kernel<<<grid, 256>>>(X, Wt, Y);
}